// round 15
// baseline (speedup 1.0000x reference)
#include <cuda_runtime.h>
#include <cstddef>

#define NN 64
#define G  16          // batches per block (half-warp lanes)
#define TB 224         // 14 half-warp roles (launch size)
#define TBMAX 256      // launch_bounds size (compile-time reg cap -> 42 -> 40)
#define BT 16384       // total batches

// global scratch (L2-resident), coalesced [n][b]; includes identity rows n=0 / n=63
__device__ float4 gvL[NN * BT];   // normalized prefix vectors
__device__ float4 gvR[NN * BT];   // normalized suffix vectors

// smem float offsets — {A, SEG, BND} live through phase 2, B overlays after
#define SA_   0                    // A [64*32]                    = 2048
#define SEG_  2048                 // 12 half-prods * 4 rows * 16g = 3072
#define SBND_ 5120                 // 32 float4                    =  128
#define SB_   0                    // B overlay [64*68]            = 4352 (< 5248)
#define SXP_  5248                 // xn float2 [64*17]            = 2176
#define SMEMF (SXP_ + 2176)        // 7424 floats = 29696 B

__device__ __forceinline__ float nan0(float h) {
    unsigned u = __float_as_uint(h);
    return ((u & 0x7fffffffu) > 0x7f800000u) ? 0.0f : h;
}

// EXACT: 1/(sqrt(d)+1e-6) — rsqrt first-order expansion blows up for the
// tiny norms raw 63-step chain products reach (R11 fail). Keep exact.
__device__ __forceinline__ float invnorm(float d) {
    return 1.0f / (sqrtf(d) + 1e-6f);
}

// build 4x4 M (row-major, 16 floats) for position nn
#define BUILD(nn, Mar)                                                         \
{                                                                              \
    float2 xp_ = sxp[(nn) * 17 + g];                                           \
    const float4* ap_ = (const float4*)(sm + SA_ + (nn) * 32);                 \
    _Pragma("unroll")                                                          \
    for (int q_ = 0; q_ < 8; ++q_) {                                           \
        float4 f_ = ap_[q_];                                                   \
        Mar[2*q_]   = fmaf(f_.x, xp_.x, f_.y * xp_.y);                         \
        Mar[2*q_+1] = fmaf(f_.z, xp_.x, f_.w * xp_.y);                         \
    }                                                                          \
}

// d = v (row) * M (row-major 16)
#define VMATA(d, v_, M)                                                        \
    d.x = fmaf(v_.x, M[0], v_.y * M[4])  + fmaf(v_.z, M[8],  v_.w * M[12]);    \
    d.y = fmaf(v_.x, M[1], v_.y * M[5])  + fmaf(v_.z, M[9],  v_.w * M[13]);    \
    d.z = fmaf(v_.x, M[2], v_.y * M[6])  + fmaf(v_.z, M[10], v_.w * M[14]);    \
    d.w = fmaf(v_.x, M[3], v_.y * M[7])  + fmaf(v_.z, M[11], v_.w * M[15]);

// d = M (row-major 16) * w (column)
#define MATVA(d, M, w_)                                                        \
    d.x = fmaf(M[0],  w_.x, M[1]  * w_.y) + fmaf(M[2],  w_.z, M[3]  * w_.w);   \
    d.y = fmaf(M[4],  w_.x, M[5]  * w_.y) + fmaf(M[6],  w_.z, M[7]  * w_.w);   \
    d.z = fmaf(M[8],  w_.x, M[9]  * w_.y) + fmaf(M[10], w_.z, M[11] * w_.w);   \
    d.w = fmaf(M[12], w_.x, M[13] * w_.y) + fmaf(M[14], w_.z, M[15] * w_.w);

// d = v (row) * [R0;R1;R2;R3]
#define VMAT4(d, v_, R0, R1, R2, R3)                                           \
    d.x = fmaf(v_.x, R0.x, v_.y * R1.x) + fmaf(v_.z, R2.x, v_.w * R3.x);       \
    d.y = fmaf(v_.x, R0.y, v_.y * R1.y) + fmaf(v_.z, R2.y, v_.w * R3.y);       \
    d.z = fmaf(v_.x, R0.z, v_.y * R1.z) + fmaf(v_.z, R2.z, v_.w * R3.z);       \
    d.w = fmaf(v_.x, R0.w, v_.y * R1.w) + fmaf(v_.z, R2.w, v_.w * R3.w);

// d = [R0;R1;R2;R3] * w (column)
#define MATV4(d, R0, R1, R2, R3, w_)                                           \
    d.x = fmaf(R0.x, w_.x, R0.y * w_.y) + fmaf(R0.z, w_.z, R0.w * w_.w);       \
    d.y = fmaf(R1.x, w_.x, R1.y * w_.y) + fmaf(R1.z, w_.z, R1.w * w_.w);       \
    d.z = fmaf(R2.x, w_.x, R2.y * w_.y) + fmaf(R2.z, w_.z, R2.w * w_.w);       \
    d.w = fmaf(R3.x, w_.x, R3.y * w_.y) + fmaf(R3.z, w_.z, R3.w * w_.w);

__global__ __launch_bounds__(TBMAX, 6)
void tdvp_kernel(const float* __restrict__ xg, const float* __restrict__ Ag,
                 const float* __restrict__ Bg, const float* __restrict__ sg,
                 float* __restrict__ yg)
{
    extern __shared__ float sm[];
    float2* sxp = (float2*)(sm + SXP_);
    const int tid = threadIdx.x;
    const int b0  = blockIdx.x * G;

    for (int i = tid; i < NN * 32; i += TB) sm[SA_ + i] = Ag[i];
    const float2* xv = (const float2*)xg;
    for (int idx = tid; idx < G * NN; idx += TB) {
        float2 v = xv[(size_t)b0 * NN + idx];
        float inv = rsqrtf(v.x * v.x + v.y * v.y);
        int bl = idx >> 6, n = idx & 63;
        sxp[n * 17 + bl] = make_float2(v.x * inv, v.y * inv);
    }
    __syncthreads();

    const int g   = tid & 15;       // batch lane
    const int rho = tid >> 4;       // role 0..13
    const int b   = b0 + g;
    float4* seg = (float4*)(sm + SEG_);
    float4* bnd = (float4*)(sm + SBND_);

    // fwd walk: build M[idx0+k], v <- v*M, store normalized gvL[idx0+k+1]
    auto fwalk = [&](int idx0, float4 v, int trips) -> float4 {
        #pragma unroll 1
        for (int k = 0; k < trips; ++k) {
            float M[16];
            BUILD(idx0 + k, M);
            float4 t; VMATA(t, v, M);
            v = t;
            float iv = invnorm(v.x*v.x + v.y*v.y + v.z*v.z + v.w*v.w);
            gvL[(idx0 + k + 1) * BT + b] = make_float4(v.x*iv, v.y*iv, v.z*iv, v.w*iv);
        }
        return v;
    };
    // bwd walk: build M[idx0-k], w <- M*w, store normalized gvR[idx0-k-1]
    auto bwalk = [&](int idx0, float4 w, int trips) -> float4 {
        #pragma unroll 1
        for (int k = 0; k < trips; ++k) {
            float M[16];
            BUILD(idx0 - k, M);
            float4 t; MATVA(t, M, w);
            w = t;
            float iv = invnorm(w.x*w.x + w.y*w.y + w.z*w.z + w.w*w.w);
            gvR[(idx0 - k - 1) * BT + b] = make_float4(w.x*iv, w.y*iv, w.z*iv, w.w*iv);
        }
        return w;
    };

    // ================= phase 1: shared half-products + walkers =================
    if (rho < 12) {
        // H_{j,half}: half 0 = M[8j..8j+3], half 1 = M[8j+4..8j+7], j = 1..6
        const int half = (rho >= 6);
        const int j    = half ? rho - 5 : rho + 1;
        const int base = 8 * j + 4 * half;
        float P[16];
        BUILD(base, P);
        #pragma unroll 1
        for (int k = 1; k < 4; ++k) {
            float M[16];
            BUILD(base + k, M);
            #pragma unroll
            for (int r2 = 0; r2 < 4; ++r2) {
                float a0 = P[r2*4], a1 = P[r2*4+1], a2 = P[r2*4+2], a3 = P[r2*4+3];
                P[r2*4+0] = fmaf(a0, M[0], a1*M[4])  + fmaf(a2, M[8],  a3*M[12]);
                P[r2*4+1] = fmaf(a0, M[1], a1*M[5])  + fmaf(a2, M[9],  a3*M[13]);
                P[r2*4+2] = fmaf(a0, M[2], a1*M[6])  + fmaf(a2, M[10], a3*M[14]);
                P[r2*4+3] = fmaf(a0, M[3], a1*M[7])  + fmaf(a2, M[11], a3*M[15]);
            }
        }
        const int slot = (j - 1) * 2 + half;
        #pragma unroll
        for (int c = 0; c < 4; ++c)
            seg[(slot*4 + c)*16 + g] = make_float4(P[4*c], P[4*c+1], P[4*c+2], P[4*c+3]);
    } else if (rho == 12) {
        gvL[b] = make_float4(1.f, 0.f, 0.f, 0.f);                  // identity n = 0
        float4 v = fwalk(0, make_float4(1.f, 0.f, 0.f, 0.f), 8);   // n = 1..8
        bnd[g] = v;                                                // raw q8
    } else {
        gvR[(NN - 1) * BT + b] = make_float4(1.f, 0.f, 0.f, 0.f);  // identity n = 63
        float4 w = bwalk(63, make_float4(1.f, 0.f, 0.f, 0.f), 8);  // n = 62..55
        bnd[16 + g] = w;                                           // raw t55
    }
    __syncthreads();

    // ================= phase 2: boundary chains + rewalks =================
    if (rho <= 6) {
        // fwd segment s = rho+1: n = 8s+1 .. 8s+8 (s=7 -> 57..63)
        const int s = rho + 1;
        float4 v = bnd[g];
        #pragma unroll 1
        for (int slot = 0; slot < 2 * (s - 1); ++slot) {
            float4 R0 = seg[(slot*4 + 0)*16 + g];
            float4 R1 = seg[(slot*4 + 1)*16 + g];
            float4 R2 = seg[(slot*4 + 2)*16 + g];
            float4 R3 = seg[(slot*4 + 3)*16 + g];
            float4 t; VMAT4(t, v, R0, R1, R2, R3);
            v = t;
        }
        fwalk(8 * s, v, (s == 7) ? 7 : 8);
    } else {
        // bwd segment s = rho-7 (0..6): boundary t(8s+7), then n = 8s+6 .. 8s
        const int s = rho - 7;
        float4 w = bnd[16 + g];
        #pragma unroll 1
        for (int j = 6; j > s; --j) {
            #pragma unroll
            for (int half = 1; half >= 0; --half) {
                const int slot = (j - 1) * 2 + half;
                float4 R0 = seg[(slot*4 + 0)*16 + g];
                float4 R1 = seg[(slot*4 + 1)*16 + g];
                float4 R2 = seg[(slot*4 + 2)*16 + g];
                float4 R3 = seg[(slot*4 + 3)*16 + g];
                float4 t; MATV4(t, R0, R1, R2, R3, w);
                w = t;
            }
        }
        {
            float iv = invnorm(w.x*w.x + w.y*w.y + w.z*w.z + w.w*w.w);
            gvR[(8*s + 7) * BT + b] = make_float4(w.x*iv, w.y*iv, w.z*iv, w.w*iv);
        }
        bwalk(8 * s + 7, w, 7);
    }
    __syncthreads();

    // ---- stage B over dead {A, SEG, BND} region (stride-68 pad) ----
    for (int i = tid; i < NN * 64; i += TB)
        sm[SB_ + (i >> 6) * 68 + (i & 63)] = Bg[i];
    __syncthreads();

    // ================= output phase: n = rho + 14k, branchless =================
    {
        const float sc = sg[0];
        #pragma unroll 1
        for (int k = 0; k < 5; ++k) {
            const int n = rho + 14 * k;
            if (n >= NN) break;

            float4 u = gvL[n * BT + b];     // identities pre-stored — no branches
            float4 a = gvR[n * BT + b];

            float uu[4] = {u.x, u.y, u.z, u.w};
            float aa[4] = {a.x, a.y, a.z, a.w};
            float H0 = 0.f, H1 = 0.f, H2 = 0.f, H3 = 0.f;
            const float* bb = sm + SB_ + n * 68;
            #pragma unroll
            for (int i2 = 0; i2 < 4; ++i2) {
                #pragma unroll
                for (int l2 = 0; l2 < 4; ++l2) {
                    float w = uu[i2] * aa[l2];
                    float4 bvv = *(const float4*)(bb + i2 * 16 + l2 * 4);  // broadcast
                    H0 = fmaf(w, bvv.x, H0);
                    H1 = fmaf(w, bvv.y, H1);
                    H2 = fmaf(w, bvv.z, H2);
                    H3 = fmaf(w, bvv.w, H3);
                }
            }

            float f    = sqrtf(H0*H0 + H1*H1 + H2*H2 + H3*H3);
            float invf = sc / (f + 1e-6f);
            H0 = fmaxf(nan0(H0 * invf), 0.f);
            H1 = fmaxf(nan0(H1 * invf), 0.f);
            H2 = fmaxf(nan0(H2 * invf), 0.f);
            H3 = fmaxf(nan0(H3 * invf), 0.f);

            float2 xp = sxp[n * 17 + g];
            float y0 = fmaf(H0, xp.x, H1 * xp.y);
            float y1 = fmaf(H2, xp.x, H3 * xp.y);
            sxp[n * 17 + g] = make_float2(y0, y1);
        }
    }
    __syncthreads();

    // ---- coalesced writeback ----
    float2* yv = (float2*)yg;
    for (int idx = tid; idx < G * NN; idx += TB) {
        int bl = idx >> 6, n = idx & 63;
        yv[(size_t)b0 * NN + idx] = sxp[n * 17 + bl];
    }
}

extern "C" void kernel_launch(void* const* d_in, const int* in_sizes, int n_in,
                              void* d_out, int out_size) {
    const float* x = (const float*)d_in[0];
    const float* A = (const float*)d_in[1];
    const float* B = (const float*)d_in[2];
    const float* s = (const float*)d_in[3];
    float* y = (float*)d_out;

    const int batch = in_sizes[0] / (NN * 2);   // 16384
    const int grid  = batch / G;                // 1024 -> single wave @ 7 CTA/SM
    const size_t smem = (size_t)SMEMF * sizeof(float);

    cudaFuncSetAttribute(tdvp_kernel, cudaFuncAttributeMaxDynamicSharedMemorySize, (int)smem);
    tdvp_kernel<<<grid, TB, smem>>>(x, A, B, s, y);
}

// round 16
// speedup vs baseline: 1.2346x; 1.2346x over previous
#include <cuda_runtime.h>
#include <cstddef>

#define NN 64
#define G  16          // batches per block (half-warp lanes)
#define TB 256         // 16 half-warp roles
#define BT 16384       // total batches

// global scratch (L2-resident), coalesced [n][b]; identity rows n=0 / n=63 pre-stored
__device__ float4 gvL[NN * BT];   // normalized prefix vectors
__device__ float4 gvR[NN * BT];   // normalized suffix vectors

// smem float offsets — {A, SEG, BND} live through phase 2, B overlays after
#define SA_   0                    // A [64*32]                    = 2048
#define SEG_  2048                 // 12 half-prods * 4 rows * 16g = 3072
#define SBND_ 5120                 // 32 float4                    =  128
#define SB_   0                    // B overlay [64*68]            = 4352 (< 5248)
#define SXP_  5248                 // xn float2 [64*17]            = 2176
#define SMEMF (SXP_ + 2176)        // 7424 floats = 29696 B

__device__ __forceinline__ float nan0(float h) {
    unsigned u = __float_as_uint(h);
    return ((u & 0x7fffffffu) > 0x7f800000u) ? 0.0f : h;
}

// EXACT: 1/(sqrt(d)+1e-6) — rsqrt expansion blows up at tiny norms (R11 fail).
__device__ __forceinline__ float invnorm(float d) {
    return 1.0f / (sqrtf(d) + 1e-6f);
}

// build 4x4 M (row-major, 16 floats) for position nn
#define BUILD(nn, Mar)                                                         \
{                                                                              \
    float2 xp_ = sxp[(nn) * 17 + g];                                           \
    const float4* ap_ = (const float4*)(sm + SA_ + (nn) * 32);                 \
    _Pragma("unroll")                                                          \
    for (int q_ = 0; q_ < 8; ++q_) {                                           \
        float4 f_ = ap_[q_];                                                   \
        Mar[2*q_]   = fmaf(f_.x, xp_.x, f_.y * xp_.y);                         \
        Mar[2*q_+1] = fmaf(f_.z, xp_.x, f_.w * xp_.y);                         \
    }                                                                          \
}

// d = v (row) * M (row-major 16)
#define VMATA(d, v_, M)                                                        \
    d.x = fmaf(v_.x, M[0], v_.y * M[4])  + fmaf(v_.z, M[8],  v_.w * M[12]);    \
    d.y = fmaf(v_.x, M[1], v_.y * M[5])  + fmaf(v_.z, M[9],  v_.w * M[13]);    \
    d.z = fmaf(v_.x, M[2], v_.y * M[6])  + fmaf(v_.z, M[10], v_.w * M[14]);    \
    d.w = fmaf(v_.x, M[3], v_.y * M[7])  + fmaf(v_.z, M[11], v_.w * M[15]);

// d = M (row-major 16) * w (column)
#define MATVA(d, M, w_)                                                        \
    d.x = fmaf(M[0],  w_.x, M[1]  * w_.y) + fmaf(M[2],  w_.z, M[3]  * w_.w);   \
    d.y = fmaf(M[4],  w_.x, M[5]  * w_.y) + fmaf(M[6],  w_.z, M[7]  * w_.w);   \
    d.z = fmaf(M[8],  w_.x, M[9]  * w_.y) + fmaf(M[10], w_.z, M[11] * w_.w);   \
    d.w = fmaf(M[12], w_.x, M[13] * w_.y) + fmaf(M[14], w_.z, M[15] * w_.w);

// d = v (row) * [R0;R1;R2;R3]
#define VMAT4(d, v_, R0, R1, R2, R3)                                           \
    d.x = fmaf(v_.x, R0.x, v_.y * R1.x) + fmaf(v_.z, R2.x, v_.w * R3.x);       \
    d.y = fmaf(v_.x, R0.y, v_.y * R1.y) + fmaf(v_.z, R2.y, v_.w * R3.y);       \
    d.z = fmaf(v_.x, R0.z, v_.y * R1.z) + fmaf(v_.z, R2.z, v_.w * R3.z);       \
    d.w = fmaf(v_.x, R0.w, v_.y * R1.w) + fmaf(v_.z, R2.w, v_.w * R3.w);

// d = [R0;R1;R2;R3] * w (column)
#define MATV4(d, R0, R1, R2, R3, w_)                                           \
    d.x = fmaf(R0.x, w_.x, R0.y * w_.y) + fmaf(R0.z, w_.z, R0.w * w_.w);       \
    d.y = fmaf(R1.x, w_.x, R1.y * w_.y) + fmaf(R1.z, w_.z, R1.w * w_.w);       \
    d.z = fmaf(R2.x, w_.x, R2.y * w_.y) + fmaf(R2.z, w_.z, R2.w * w_.w);       \
    d.w = fmaf(R3.x, w_.x, R3.y * w_.y) + fmaf(R3.z, w_.z, R3.w * w_.w);

__global__ __launch_bounds__(TB, 6)
void tdvp_kernel(const float* __restrict__ xg, const float* __restrict__ Ag,
                 const float* __restrict__ Bg, const float* __restrict__ sg,
                 float* __restrict__ yg)
{
    extern __shared__ float sm[];
    float2* sxp = (float2*)(sm + SXP_);
    const int tid = threadIdx.x;
    const int b0  = blockIdx.x * G;

    for (int i = tid; i < NN * 32; i += TB) sm[SA_ + i] = Ag[i];
    const float2* xv = (const float2*)xg;
    for (int idx = tid; idx < G * NN; idx += TB) {
        float2 v = xv[(size_t)b0 * NN + idx];
        float inv = rsqrtf(v.x * v.x + v.y * v.y);
        int bl = idx >> 6, n = idx & 63;
        sxp[n * 17 + bl] = make_float2(v.x * inv, v.y * inv);
    }
    __syncthreads();

    const int g   = tid & 15;       // batch lane
    const int rho = tid >> 4;       // role 0..15
    const int b   = b0 + g;
    float4* seg = (float4*)(sm + SEG_);
    float4* bnd = (float4*)(sm + SBND_);

    // fwd walk: build M[idx0+k], v <- v*M, store normalized gvL[idx0+k+1]
    auto fwalk = [&](int idx0, float4 v, int trips) -> float4 {
        #pragma unroll 1
        for (int k = 0; k < trips; ++k) {
            float M[16];
            BUILD(idx0 + k, M);
            float4 t; VMATA(t, v, M);
            v = t;
            float iv = invnorm(v.x*v.x + v.y*v.y + v.z*v.z + v.w*v.w);
            gvL[(idx0 + k + 1) * BT + b] = make_float4(v.x*iv, v.y*iv, v.z*iv, v.w*iv);
        }
        return v;
    };
    // bwd walk: build M[idx0-k], w <- M*w, store normalized gvR[idx0-k-1]
    auto bwalk = [&](int idx0, float4 w, int trips) -> float4 {
        #pragma unroll 1
        for (int k = 0; k < trips; ++k) {
            float M[16];
            BUILD(idx0 - k, M);
            float4 t; MATVA(t, M, w);
            w = t;
            float iv = invnorm(w.x*w.x + w.y*w.y + w.z*w.z + w.w*w.w);
            gvR[(idx0 - k - 1) * BT + b] = make_float4(w.x*iv, w.y*iv, w.z*iv, w.w*iv);
        }
        return w;
    };

    // ====== phase 1: shared half-products + walkers (walkers in SEPARATE warps) ======
    if (rho < 12) {
        // H_{j,half}: half 0 = M[8j..8j+3], half 1 = M[8j+4..8j+7], j = 1..6
        const int half = (rho >= 6);
        const int j    = half ? rho - 5 : rho + 1;
        const int base = 8 * j + 4 * half;
        float P[16];
        BUILD(base, P);
        #pragma unroll 1
        for (int k = 1; k < 4; ++k) {
            float M[16];
            BUILD(base + k, M);
            #pragma unroll
            for (int r2 = 0; r2 < 4; ++r2) {
                float a0 = P[r2*4], a1 = P[r2*4+1], a2 = P[r2*4+2], a3 = P[r2*4+3];
                P[r2*4+0] = fmaf(a0, M[0], a1*M[4])  + fmaf(a2, M[8],  a3*M[12]);
                P[r2*4+1] = fmaf(a0, M[1], a1*M[5])  + fmaf(a2, M[9],  a3*M[13]);
                P[r2*4+2] = fmaf(a0, M[2], a1*M[6])  + fmaf(a2, M[10], a3*M[14]);
                P[r2*4+3] = fmaf(a0, M[3], a1*M[7])  + fmaf(a2, M[11], a3*M[15]);
            }
        }
        const int slot = (j - 1) * 2 + half;
        #pragma unroll
        for (int c = 0; c < 4; ++c)
            seg[(slot*4 + c)*16 + g] = make_float4(P[4*c], P[4*c+1], P[4*c+2], P[4*c+3]);
    } else if (rho == 12) {
        float4 v = fwalk(0, make_float4(1.f, 0.f, 0.f, 0.f), 8);   // n = 1..8
        bnd[g] = v;                                                // raw q8
    } else if (rho == 14) {
        float4 w = bwalk(63, make_float4(1.f, 0.f, 0.f, 0.f), 8);  // n = 62..55
        bnd[16 + g] = w;                                           // raw t55
    } else if (rho == 13) {
        gvL[b] = make_float4(1.f, 0.f, 0.f, 0.f);                  // identity n = 0
    } else {
        gvR[(NN - 1) * BT + b] = make_float4(1.f, 0.f, 0.f, 0.f);  // identity n = 63
    }
    __syncthreads();

    // ================= phase 2: boundary chains + rewalks =================
    if (rho <= 6) {
        // fwd segment s = rho+1: n = 8s+1 .. 8s+8 (s=7 -> 57..63)
        const int s = rho + 1;
        float4 v = bnd[g];
        #pragma unroll 1
        for (int slot = 0; slot < 2 * (s - 1); ++slot) {
            float4 R0 = seg[(slot*4 + 0)*16 + g];
            float4 R1 = seg[(slot*4 + 1)*16 + g];
            float4 R2 = seg[(slot*4 + 2)*16 + g];
            float4 R3 = seg[(slot*4 + 3)*16 + g];
            float4 t; VMAT4(t, v, R0, R1, R2, R3);
            v = t;
        }
        fwalk(8 * s, v, (s == 7) ? 7 : 8);
    } else if (rho >= 8 && rho <= 14) {
        // bwd segment s = rho-8 (0..6): boundary t(8s+7), then n = 8s+6 .. 8s
        const int s = rho - 8;
        float4 w = bnd[16 + g];
        #pragma unroll 1
        for (int j = 6; j > s; --j) {
            #pragma unroll
            for (int half = 1; half >= 0; --half) {
                const int slot = (j - 1) * 2 + half;
                float4 R0 = seg[(slot*4 + 0)*16 + g];
                float4 R1 = seg[(slot*4 + 1)*16 + g];
                float4 R2 = seg[(slot*4 + 2)*16 + g];
                float4 R3 = seg[(slot*4 + 3)*16 + g];
                float4 t; MATV4(t, R0, R1, R2, R3, w);
                w = t;
            }
        }
        {
            float iv = invnorm(w.x*w.x + w.y*w.y + w.z*w.z + w.w*w.w);
            gvR[(8*s + 7) * BT + b] = make_float4(w.x*iv, w.y*iv, w.z*iv, w.w*iv);
        }
        bwalk(8 * s + 7, w, 7);
    }
    __syncthreads();

    // ---- stage B over dead {A, SEG, BND} region (stride-68 pad) ----
    for (int i = tid; i < NN * 64; i += TB)
        sm[SB_ + (i >> 6) * 68 + (i & 63)] = Bg[i];
    __syncthreads();

    // ====== output phase: n = rho*4 + k, branchless, x2-hoisted gv loads ======
    {
        const float sc = sg[0];
        #pragma unroll 1
        for (int k = 0; k < 4; k += 2) {
            const int n0 = rho * 4 + k;
            const int n1 = n0 + 1;
            float4 u0 = gvL[n0 * BT + b];
            float4 a0 = gvR[n0 * BT + b];
            float4 u1 = gvL[n1 * BT + b];
            float4 a1 = gvR[n1 * BT + b];

            #pragma unroll
            for (int t2 = 0; t2 < 2; ++t2) {
                const int n = t2 ? n1 : n0;
                float4 u = t2 ? u1 : u0;
                float4 a = t2 ? a1 : a0;
                float uu[4] = {u.x, u.y, u.z, u.w};
                float aa[4] = {a.x, a.y, a.z, a.w};
                float H0 = 0.f, H1 = 0.f, H2 = 0.f, H3 = 0.f;
                const float* bb = sm + SB_ + n * 68;
                #pragma unroll
                for (int i2 = 0; i2 < 4; ++i2) {
                    #pragma unroll
                    for (int l2 = 0; l2 < 4; ++l2) {
                        float w = uu[i2] * aa[l2];
                        float4 bvv = *(const float4*)(bb + i2 * 16 + l2 * 4);  // broadcast
                        H0 = fmaf(w, bvv.x, H0);
                        H1 = fmaf(w, bvv.y, H1);
                        H2 = fmaf(w, bvv.z, H2);
                        H3 = fmaf(w, bvv.w, H3);
                    }
                }

                float f    = sqrtf(H0*H0 + H1*H1 + H2*H2 + H3*H3);
                float invf = sc / (f + 1e-6f);
                H0 = fmaxf(nan0(H0 * invf), 0.f);
                H1 = fmaxf(nan0(H1 * invf), 0.f);
                H2 = fmaxf(nan0(H2 * invf), 0.f);
                H3 = fmaxf(nan0(H3 * invf), 0.f);

                float2 xp = sxp[n * 17 + g];
                float y0 = fmaf(H0, xp.x, H1 * xp.y);
                float y1 = fmaf(H2, xp.x, H3 * xp.y);
                sxp[n * 17 + g] = make_float2(y0, y1);
            }
        }
    }
    __syncthreads();

    // ---- coalesced writeback ----
    float2* yv = (float2*)yg;
    for (int idx = tid; idx < G * NN; idx += TB) {
        int bl = idx >> 6, n = idx & 63;
        yv[(size_t)b0 * NN + idx] = sxp[n * 17 + bl];
    }
}

extern "C" void kernel_launch(void* const* d_in, const int* in_sizes, int n_in,
                              void* d_out, int out_size) {
    const float* x = (const float*)d_in[0];
    const float* A = (const float*)d_in[1];
    const float* B = (const float*)d_in[2];
    const float* s = (const float*)d_in[3];
    float* y = (float*)d_out;

    const int batch = in_sizes[0] / (NN * 2);   // 16384
    const int grid  = batch / G;                // 1024
    const size_t smem = (size_t)SMEMF * sizeof(float);

    cudaFuncSetAttribute(tdvp_kernel, cudaFuncAttributeMaxDynamicSharedMemorySize, (int)smem);
    tdvp_kernel<<<grid, TB, smem>>>(x, A, B, s, y);
}